// round 11
// baseline (speedup 1.0000x reference)
#include <cuda_runtime.h>
#include <cuda_fp16.h>
#include <math.h>
#include <stdint.h>

// Problem constants
#define Bq   4
#define Lq   4096
#define Dq   1024
#define Hq   16
#define Wq   64
#define HDq  64
#define Mrows (Bq*Lq)          // 16384

// Scratch buffers (device globals)
__device__ __half g_xh[(size_t)Mrows * Dq];          // 32 MB
__device__ __half g_wqkvh[(size_t)3 * Dq * Dq];      // 6 MB
__device__ __half g_wprojh[(size_t)Dq * Dq];         // 2 MB
__device__ __half g_qkvh[(size_t)Mrows * 3 * Dq];    // 96 MB
__device__ __half g_attnh[(size_t)Mrows * Dq];       // 32 MB
__device__ float  g_y[(size_t)Mrows * Dq];           // 64 MB

// ---------------------------------------------------------------------------
// Helpers
// ---------------------------------------------------------------------------
__device__ __forceinline__ uint32_t smem_u32(const void* p) {
    return (uint32_t)__cvta_generic_to_shared(p);
}
__device__ __forceinline__ void cp16(uint32_t s, const void* g) {
    asm volatile("cp.async.cg.shared.global [%0], [%1], 16;" :: "r"(s), "l"(g));
}
__device__ __forceinline__ void ldsm_x4(uint32_t r[4], uint32_t addr) {
    asm volatile("ldmatrix.sync.aligned.m8n8.x4.shared.b16 {%0,%1,%2,%3}, [%4];"
                 : "=r"(r[0]), "=r"(r[1]), "=r"(r[2]), "=r"(r[3]) : "r"(addr));
}
__device__ __forceinline__ void ldsm_x4_t(uint32_t r[4], uint32_t addr) {
    asm volatile("ldmatrix.sync.aligned.m8n8.x4.trans.shared.b16 {%0,%1,%2,%3}, [%4];"
                 : "=r"(r[0]), "=r"(r[1]), "=r"(r[2]), "=r"(r[3]) : "r"(addr));
}
__device__ __forceinline__ void mma_f16(float c[4], const uint32_t a[4],
                                        uint32_t b0, uint32_t b1) {
    asm volatile(
        "mma.sync.aligned.m16n8k16.row.col.f32.f16.f16.f32 "
        "{%0,%1,%2,%3}, {%4,%5,%6,%7}, {%8,%9}, {%0,%1,%2,%3};"
        : "+f"(c[0]), "+f"(c[1]), "+f"(c[2]), "+f"(c[3])
        : "r"(a[0]), "r"(a[1]), "r"(a[2]), "r"(a[3]), "r"(b0), "r"(b1));
}
__device__ __forceinline__ uint32_t h2u(float x, float y) {
    __half2 h = __floats2half2_rn(x, y);
    return *(uint32_t*)&h;
}

// ---------------------------------------------------------------------------
// fp32 -> fp16 conversion (grid-stride, 8 elems/thread)
// ---------------------------------------------------------------------------
__global__ __launch_bounds__(256, 1)
void f2h_kernel(const float* __restrict__ src, __half* __restrict__ dst, int n)
{
    int i = (blockIdx.x * 256 + threadIdx.x) * 8;
    if (i >= n) return;
    float4 v0 = *(const float4*)(src + i);
    float4 v1 = *(const float4*)(src + i + 4);
    __half2 h[4];
    h[0] = __floats2half2_rn(v0.x, v0.y);
    h[1] = __floats2half2_rn(v0.z, v0.w);
    h[2] = __floats2half2_rn(v1.x, v1.y);
    h[3] = __floats2half2_rn(v1.z, v1.w);
    *(uint4*)(dst + i) = *(uint4*)h;
}

// ---------------------------------------------------------------------------
// fp16 mma GEMM (NT): C[m][n] = sum_k A[m][k]*B[n][k] + bias[n] (+res)
// CTA 128x128x64(halfs), 128 thr: 4 warps in 2x2, each 64x64 warp tile.
// Per k16-step per warp: 8 LDSM -> 32 independent MMAs (4:1 density).
// 3-stage cp.async; SMEM rows padded to 72 halfs (144 B, ldmatrix
// conflict-free). Output fp16 (Ch) or fp32+residual (Cf).
// ---------------------------------------------------------------------------
#define BMh 128
#define BNh 128
#define BKh 64
#define HSTR 72                                // halfs per padded row
#define ROWB (HSTR * 2)                        // 144 bytes per row
#define STG_BYTES_H (2 * 128 * ROWB)           // 36864 B per stage
#define GEMM_SMEM_H (3 * STG_BYTES_H)          // 110592 B

__global__ __launch_bounds__(128, 2)
void hgemm(const __half* __restrict__ A, const __half* __restrict__ B,
           const float* __restrict__ bias, const float* __restrict__ res,
           __half* __restrict__ Ch, float* __restrict__ Cf, int N, int K)
{
    extern __shared__ __half hsm[];

    const int tid = threadIdx.x;
    const int wid = tid >> 5, lid = tid & 31;
    const int wm = (wid >> 1) * 64;     // warp m offset (2x2 warp grid)
    const int wn = (wid & 1) * 64;      // warp n offset

    const int bn = blockIdx.x, bm = blockIdx.y;
    const __half* Ab = A + (size_t)bm * BMh * K;
    const __half* Bb = B + (size_t)bn * BNh * K;
    const int NIT = K / BKh;            // 16 for K=1024

    const uint32_t sb = smem_u32(hsm);

    // Stage loader: A 128x64h + B 128x64h = 2048 x 16B chunks, 16/thread.
    auto issue = [&](int it) {
        uint32_t stg = sb + (uint32_t)(it % 3) * STG_BYTES_H;
        const __half* Ag = Ab + it * BKh;
        const __half* Bg = Bb + it * BKh;
        #pragma unroll
        for (int f = tid; f < 2048; f += 128) {
            int r = (f >> 3) & 127;
            int c = f & 7;
            const __half* src;
            uint32_t dst;
            if (f < 1024) {
                src = Ag + (size_t)r * K + c * 8;
                dst = stg + (uint32_t)(r * ROWB + c * 16);
            } else {
                src = Bg + (size_t)r * K + c * 8;
                dst = stg + (uint32_t)(128 * ROWB + r * ROWB + c * 16);
            }
            cp16(dst, src);
        }
        asm volatile("cp.async.commit_group;" ::: "memory");
    };

    float acc[4][8][4];
    #pragma unroll
    for (int i = 0; i < 4; i++)
        #pragma unroll
        for (int j = 0; j < 8; j++)
            #pragma unroll
            for (int t = 0; t < 4; t++) acc[i][j][t] = 0.f;

    issue(0);
    issue(1);

    // ldmatrix lane address components
    const int a_row = lid & 15;                       // + wm + 16*mi
    const int a_kh  = (lid >> 4) << 3;                // k offset (halfs)
    const int b_row = ((lid >> 4) << 3) + (lid & 7);  // + wn + 16*bj
    const int b_kh  = ((lid >> 3) & 1) << 3;

    for (int it = 0; it < NIT; ++it) {
        if (it + 2 < NIT) {
            issue(it + 2);
            asm volatile("cp.async.wait_group 2;" ::: "memory");
        } else if (it + 1 < NIT) {
            asm volatile("cp.async.wait_group 1;" ::: "memory");
        } else {
            asm volatile("cp.async.wait_group 0;" ::: "memory");
        }
        __syncthreads();

        uint32_t smA = sb + (uint32_t)(it % 3) * STG_BYTES_H;
        uint32_t smB = smA + 128 * ROWB;

        #pragma unroll
        for (int k16 = 0; k16 < BKh; k16 += 16) {
            uint32_t a[4][4], bf[4][4];
            #pragma unroll
            for (int mi = 0; mi < 4; mi++)
                ldsm_x4(a[mi], smA + (uint32_t)((wm + 16 * mi + a_row) * ROWB
                                                + (k16 + a_kh) * 2));
            #pragma unroll
            for (int bj = 0; bj < 4; bj++)
                ldsm_x4(bf[bj], smB + (uint32_t)((wn + 16 * bj + b_row) * ROWB
                                                 + (k16 + b_kh) * 2));
            #pragma unroll
            for (int mi = 0; mi < 4; mi++) {
                #pragma unroll
                for (int nj = 0; nj < 8; nj++) {
                    int bj = nj >> 1, hi = (nj & 1) << 1;
                    mma_f16(acc[mi][nj], a[mi], bf[bj][hi], bf[bj][hi + 1]);
                }
            }
        }
        __syncthreads();
    }

    // Epilogue
    const int g = lid >> 2, tg = lid & 3;
    #pragma unroll
    for (int mi = 0; mi < 4; mi++) {
        const int row0 = bm * BMh + wm + 16 * mi + g;
        #pragma unroll
        for (int nj = 0; nj < 8; nj++) {
            const int col = bn * BNh + wn + nj * 8 + 2 * tg;
            float bx = bias[col], by = bias[col + 1];
            float v0 = acc[mi][nj][0] + bx, v1 = acc[mi][nj][1] + by;
            float v2 = acc[mi][nj][2] + bx, v3 = acc[mi][nj][3] + by;
            if (Ch) {
                *(__half2*)(Ch + (size_t)row0 * N + col) = __floats2half2_rn(v0, v1);
                *(__half2*)(Ch + (size_t)(row0 + 8) * N + col) = __floats2half2_rn(v2, v3);
            } else {
                float2 r0 = *(const float2*)(res + (size_t)row0 * N + col);
                float2 r1 = *(const float2*)(res + (size_t)(row0 + 8) * N + col);
                float2 o0 = make_float2(v0 + r0.x, v1 + r0.y);
                float2 o1 = make_float2(v2 + r1.x, v3 + r1.y);
                *(float2*)(Cf + (size_t)row0 * N + col) = o0;
                *(float2*)(Cf + (size_t)(row0 + 8) * N + col) = o1;
            }
        }
    }
}

// ---------------------------------------------------------------------------
// Tensor-core windowed attention: one CTA per (b, h, window), 4 warps.
// ---------------------------------------------------------------------------
__global__ __launch_bounds__(128, 1)
void win_attn_tc(const __half* __restrict__ qkv, __half* __restrict__ outp)
{
    __shared__ __half Qs[64 * HSTR], Ks[64 * HSTR], Vs[64 * HSTR];

    const int tid = threadIdx.x, wid = tid >> 5, lid = tid & 31;
    const int w = blockIdx.x & 63;
    const int h = (blockIdx.x >> 6) & 15;
    const int b = blockIdx.x >> 10;

    const size_t base = ((size_t)(b * Lq + w * Wq)) * (3 * Dq) + h * HDq;

    #pragma unroll
    for (int f = tid; f < 512; f += 128) {
        int row = f >> 3;
        int cq = (f & 7) << 3;
        size_t gg = base + (size_t)row * (3 * Dq) + cq;
        *(uint4*)(Qs + row * HSTR + cq) = *(const uint4*)(qkv + gg);
        *(uint4*)(Ks + row * HSTR + cq) = *(const uint4*)(qkv + gg + Dq);
        *(uint4*)(Vs + row * HSTR + cq) = *(const uint4*)(qkv + gg + 2 * Dq);
    }
    __syncthreads();

    const int g = lid >> 2, tg = lid & 3;
    const int m0 = wid * 16;
    const int a_row = lid & 15;
    const int a_kh  = (lid >> 4) << 3;
    const int b_row = ((lid >> 4) << 3) + (lid & 7);
    const int b_kh  = ((lid >> 3) & 1) << 3;

    const uint32_t qb = smem_u32(Qs), kb2_ = smem_u32(Ks), vb = smem_u32(Vs);

    // Phase 1: S = Q K^T  (warp: m16 x n64 x k64)
    float accS[8][4];
    #pragma unroll
    for (int nj = 0; nj < 8; nj++)
        #pragma unroll
        for (int t = 0; t < 4; t++) accS[nj][t] = 0.f;

    #pragma unroll
    for (int kb = 0; kb < 4; kb++) {
        uint32_t a[4];
        ldsm_x4(a, qb + (uint32_t)((m0 + a_row) * ROWB + (kb * 16 + a_kh) * 2));
        #pragma unroll
        for (int bj = 0; bj < 4; bj++) {
            uint32_t bf[4];
            ldsm_x4(bf, kb2_ + (uint32_t)((16 * bj + b_row) * ROWB
                                          + (kb * 16 + b_kh) * 2));
            mma_f16(accS[2 * bj],     a, bf[0], bf[1]);
            mma_f16(accS[2 * bj + 1], a, bf[2], bf[3]);
        }
    }

    // Softmax in registers. Rows: ra = m0+g (c0,c1), rb = m0+g+8 (c2,c3).
    const float scale = 0.125f;
    float mxa = -1e30f, mxb = -1e30f;
    #pragma unroll
    for (int nj = 0; nj < 8; nj++) {
        #pragma unroll
        for (int t = 0; t < 4; t++) accS[nj][t] *= scale;
        mxa = fmaxf(mxa, fmaxf(accS[nj][0], accS[nj][1]));
        mxb = fmaxf(mxb, fmaxf(accS[nj][2], accS[nj][3]));
    }
    mxa = fmaxf(mxa, __shfl_xor_sync(0xffffffffu, mxa, 1));
    mxa = fmaxf(mxa, __shfl_xor_sync(0xffffffffu, mxa, 2));
    mxb = fmaxf(mxb, __shfl_xor_sync(0xffffffffu, mxb, 1));
    mxb = fmaxf(mxb, __shfl_xor_sync(0xffffffffu, mxb, 2));

    float suma = 0.f, sumb = 0.f;
    #pragma unroll
    for (int nj = 0; nj < 8; nj++) {
        accS[nj][0] = __expf(accS[nj][0] - mxa);
        accS[nj][1] = __expf(accS[nj][1] - mxa);
        accS[nj][2] = __expf(accS[nj][2] - mxb);
        accS[nj][3] = __expf(accS[nj][3] - mxb);
        suma += accS[nj][0] + accS[nj][1];
        sumb += accS[nj][2] + accS[nj][3];
    }
    suma += __shfl_xor_sync(0xffffffffu, suma, 1);
    suma += __shfl_xor_sync(0xffffffffu, suma, 2);
    sumb += __shfl_xor_sync(0xffffffffu, sumb, 1);
    sumb += __shfl_xor_sync(0xffffffffu, sumb, 2);
    const float inva = 1.f / suma, invb = 1.f / sumb;

    // Repack P into fp16 a-fragments
    uint32_t pa[4][4];
    #pragma unroll
    for (int kb2 = 0; kb2 < 4; kb2++) {
        pa[kb2][0] = h2u(accS[2 * kb2][0] * inva,     accS[2 * kb2][1] * inva);
        pa[kb2][1] = h2u(accS[2 * kb2][2] * invb,     accS[2 * kb2][3] * invb);
        pa[kb2][2] = h2u(accS[2 * kb2 + 1][0] * inva, accS[2 * kb2 + 1][1] * inva);
        pa[kb2][3] = h2u(accS[2 * kb2 + 1][2] * invb, accS[2 * kb2 + 1][3] * invb);
    }

    // Phase 2: O = P V
    float accO[8][4];
    #pragma unroll
    for (int nj = 0; nj < 8; nj++)
        #pragma unroll
        for (int t = 0; t < 4; t++) accO[nj][t] = 0.f;

    const int v_row = ((lid >> 3) & 1) * 8 + (lid & 7);   // + kb2*16
    const int v_col = ((lid >> 4) & 1) * 8;               // + 16*t

    #pragma unroll
    for (int kb2 = 0; kb2 < 4; kb2++) {
        #pragma unroll
        for (int t = 0; t < 4; t++) {
            uint32_t vf[4];
            ldsm_x4_t(vf, vb + (uint32_t)((kb2 * 16 + v_row) * ROWB
                                          + (16 * t + v_col) * 2));
            mma_f16(accO[2 * t],     pa[kb2], vf[0], vf[1]);
            mma_f16(accO[2 * t + 1], pa[kb2], vf[2], vf[3]);
        }
    }

    // Store O rows (fp16)
    const int orow = b * Lq + w * Wq + m0;
    #pragma unroll
    for (int nj = 0; nj < 8; nj++) {
        const int col = h * HDq + 8 * nj + 2 * tg;
        __half2 lo = __floats2half2_rn(accO[nj][0], accO[nj][1]);
        __half2 hi = __floats2half2_rn(accO[nj][2], accO[nj][3]);
        *(__half2*)(outp + (size_t)(orow + g) * Dq + col) = lo;
        *(__half2*)(outp + (size_t)(orow + g + 8) * Dq + col) = hi;
    }
}

// ---------------------------------------------------------------------------
// LayerNorm: one block per row (1024 elems, 256 threads x 4)
// ---------------------------------------------------------------------------
__global__ __launch_bounds__(256, 1)
void layernorm_k(const float* __restrict__ y, const float* __restrict__ gamma,
                 const float* __restrict__ beta, float* __restrict__ out)
{
    __shared__ float r1[8], r2[8];
    const int row = blockIdx.x;
    const int tid = threadIdx.x;
    const float* yr = y + (size_t)row * Dq;
    const int c = tid * 4;

    float4 v = *(const float4*)(yr + c);
    float s = v.x + v.y + v.z + v.w;
    #pragma unroll
    for (int o = 16; o; o >>= 1) s += __shfl_xor_sync(0xffffffffu, s, o);
    if ((tid & 31) == 0) r1[tid >> 5] = s;
    __syncthreads();

    float mean = 0.f;
    #pragma unroll
    for (int i = 0; i < 8; i++) mean += r1[i];
    mean *= (1.f / 1024.f);

    float dx = v.x - mean, dy = v.y - mean, dz = v.z - mean, dw = v.w - mean;
    float ss = dx * dx + dy * dy + dz * dz + dw * dw;
    #pragma unroll
    for (int o = 16; o; o >>= 1) ss += __shfl_xor_sync(0xffffffffu, ss, o);
    if ((tid & 31) == 0) r2[tid >> 5] = ss;
    __syncthreads();

    float var = 0.f;
    #pragma unroll
    for (int i = 0; i < 8; i++) var += r2[i];
    var *= (1.f / 1024.f);
    float inv = rsqrtf(var + 1e-5f);

    float4 gm = *(const float4*)(gamma + c);
    float4 bt = *(const float4*)(beta + c);
    float4 o4;
    o4.x = dx * inv * gm.x + bt.x;
    o4.y = dy * inv * gm.y + bt.y;
    o4.z = dz * inv * gm.z + bt.z;
    o4.w = dw * inv * gm.w + bt.w;
    *(float4*)(out + (size_t)row * Dq + c) = o4;
}

// ---------------------------------------------------------------------------
extern "C" void kernel_launch(void* const* d_in, const int* in_sizes, int n_in,
                              void* d_out, int out_size)
{
    const float* x     = (const float*)d_in[0];
    const float* Wqkv  = (const float*)d_in[1];
    const float* bqkv  = (const float*)d_in[2];
    const float* Wproj = (const float*)d_in[3];
    const float* bproj = (const float*)d_in[4];
    const float* gamma = (const float*)d_in[5];
    const float* beta  = (const float*)d_in[6];
    float* out = (float*)d_out;

    __half *xh, *wqkvh, *wprojh, *qkvh, *attnh;
    float* y;
    cudaGetSymbolAddress((void**)&xh,     g_xh);
    cudaGetSymbolAddress((void**)&wqkvh,  g_wqkvh);
    cudaGetSymbolAddress((void**)&wprojh, g_wprojh);
    cudaGetSymbolAddress((void**)&qkvh,   g_qkvh);
    cudaGetSymbolAddress((void**)&attnh,  g_attnh);
    cudaGetSymbolAddress((void**)&y,      g_y);

    cudaFuncSetAttribute(hgemm, cudaFuncAttributeMaxDynamicSharedMemorySize, GEMM_SMEM_H);

    // 0) fp32 -> fp16 conversions
    f2h_kernel<<<(Mrows * Dq) / 2048, 256>>>(x, xh, Mrows * Dq);
    f2h_kernel<<<(3 * Dq * Dq) / 2048, 256>>>(Wqkv, wqkvh, 3 * Dq * Dq);
    f2h_kernel<<<(Dq * Dq) / 2048, 256>>>(Wproj, wprojh, Dq * Dq);

    // 1) QKV projection -> fp16 qkv
    hgemm<<<dim3(3 * Dq / BNh, Mrows / BMh), 128, GEMM_SMEM_H>>>(
        xh, wqkvh, bqkv, nullptr, qkvh, nullptr, 3 * Dq, Dq);
    // 2) Windowed attention (tensor cores) -> fp16 attn
    win_attn_tc<<<Bq * Hq * (Lq / Wq), 128>>>(qkvh, attnh);
    // 3) Output projection + bias + residual -> fp32 y
    hgemm<<<dim3(Dq / BNh, Mrows / BMh), 128, GEMM_SMEM_H>>>(
        attnh, wprojh, bproj, x, nullptr, y, Dq, Dq);
    // 4) LayerNorm -> out
    layernorm_k<<<Mrows, 256>>>(y, gamma, beta, out);
}

// round 12
// speedup vs baseline: 1.5499x; 1.5499x over previous
#include <cuda_runtime.h>
#include <cuda_fp16.h>
#include <math.h>
#include <stdint.h>

// Problem constants
#define Bq   4
#define Lq   4096
#define Dq   1024
#define Hq   16
#define Wq   64
#define HDq  64
#define Mrows (Bq*Lq)          // 16384

// Scratch buffers (device globals)
__device__ __half g_xh[(size_t)Mrows * Dq];          // 32 MB
__device__ __half g_wqkvh[(size_t)3 * Dq * Dq];      // 6 MB
__device__ __half g_wprojh[(size_t)Dq * Dq];         // 2 MB
__device__ __half g_qkvh[(size_t)Mrows * 3 * Dq];    // 96 MB
__device__ __half g_attnh[(size_t)Mrows * Dq];       // 32 MB
__device__ float  g_y[(size_t)Mrows * Dq];           // 64 MB

// ---------------------------------------------------------------------------
// Helpers
// ---------------------------------------------------------------------------
__device__ __forceinline__ uint32_t smem_u32(const void* p) {
    return (uint32_t)__cvta_generic_to_shared(p);
}
__device__ __forceinline__ void cp16(uint32_t s, const void* g) {
    asm volatile("cp.async.cg.shared.global [%0], [%1], 16;" :: "r"(s), "l"(g));
}
__device__ __forceinline__ void ldsm_x4(uint32_t r[4], uint32_t addr) {
    asm volatile("ldmatrix.sync.aligned.m8n8.x4.shared.b16 {%0,%1,%2,%3}, [%4];"
                 : "=r"(r[0]), "=r"(r[1]), "=r"(r[2]), "=r"(r[3]) : "r"(addr));
}
__device__ __forceinline__ void ldsm_x4_t(uint32_t r[4], uint32_t addr) {
    asm volatile("ldmatrix.sync.aligned.m8n8.x4.trans.shared.b16 {%0,%1,%2,%3}, [%4];"
                 : "=r"(r[0]), "=r"(r[1]), "=r"(r[2]), "=r"(r[3]) : "r"(addr));
}
__device__ __forceinline__ void mma_f16(float c[4], const uint32_t a[4],
                                        uint32_t b0, uint32_t b1) {
    asm volatile(
        "mma.sync.aligned.m16n8k16.row.col.f32.f16.f16.f32 "
        "{%0,%1,%2,%3}, {%4,%5,%6,%7}, {%8,%9}, {%0,%1,%2,%3};"
        : "+f"(c[0]), "+f"(c[1]), "+f"(c[2]), "+f"(c[3])
        : "r"(a[0]), "r"(a[1]), "r"(a[2]), "r"(a[3]), "r"(b0), "r"(b1));
}
__device__ __forceinline__ uint32_t h2u(float x, float y) {
    __half2 h = __floats2half2_rn(x, y);
    return *(uint32_t*)&h;
}

// ---------------------------------------------------------------------------
// Fused fp32 -> fp16 conversion for x, Wqkv, Wproj (one launch)
// ---------------------------------------------------------------------------
#define N_X   (Mrows * Dq)          // 16777216
#define N_WQ  (3 * Dq * Dq)         // 3145728
#define N_WP  (Dq * Dq)             // 1048576
#define N_CVT (N_X + N_WQ + N_WP)   // 20971520

__global__ __launch_bounds__(256, 1)
void f2h_all(const float* __restrict__ x, const float* __restrict__ wq,
             const float* __restrict__ wp, __half* __restrict__ xh,
             __half* __restrict__ wqh, __half* __restrict__ wph)
{
    int i = (blockIdx.x * 256 + threadIdx.x) * 8;
    const float* src;
    __half* dst;
    if (i < N_X)            { src = x + i;              dst = xh + i; }
    else if (i < N_X + N_WQ){ src = wq + (i - N_X);     dst = wqh + (i - N_X); }
    else                    { src = wp + (i - N_X - N_WQ); dst = wph + (i - N_X - N_WQ); }
    float4 v0 = *(const float4*)(src);
    float4 v1 = *(const float4*)(src + 4);
    __half2 h[4];
    h[0] = __floats2half2_rn(v0.x, v0.y);
    h[1] = __floats2half2_rn(v0.z, v0.w);
    h[2] = __floats2half2_rn(v1.x, v1.y);
    h[3] = __floats2half2_rn(v1.z, v1.w);
    *(uint4*)(dst) = *(uint4*)h;
}

// ---------------------------------------------------------------------------
// fp16 mma GEMM (NT): C[m][n] = sum_k A[m][k]*B[n][k] + bias[n] (+res)
// CTA 128x128x64(halfs), 256 thr (8 warps 2x4, 64x32 warp tiles), 2-stage
// cp.async ping-pong. SMEM rows padded to 72 halfs (144 B): ldmatrix
// conflict-free. (Best measured config: 302 us on GEMM1.)
// ---------------------------------------------------------------------------
#define BMh 128
#define BNh 128
#define BKh 64
#define HSTR 72                                // halfs per padded row
#define ROWB (HSTR * 2)                        // 144 bytes per row
#define STG_BYTES_H (2 * 128 * ROWB)           // 36864 B per stage
#define GEMM_SMEM_H (2 * STG_BYTES_H)          // 73728 B

__global__ __launch_bounds__(256, 2)
void hgemm(const __half* __restrict__ A, const __half* __restrict__ B,
           const float* __restrict__ bias, const float* __restrict__ res,
           __half* __restrict__ Ch, float* __restrict__ Cf, int N, int K)
{
    extern __shared__ __half hsm[];

    const int tid = threadIdx.x;
    const int wid = tid >> 5, lid = tid & 31;
    const int wm = (wid >> 2) * 64;
    const int wn = (wid & 3) * 32;

    const int bn = blockIdx.x, bm = blockIdx.y;
    const __half* Ab = A + (size_t)bm * BMh * K;
    const __half* Bb = B + (size_t)bn * BNh * K;
    const int NIT = K / BKh;                   // 16 for K=1024

    const uint32_t sb = smem_u32(hsm);

    auto issue = [&](int it) {
        uint32_t stg = sb + (uint32_t)(it & 1) * STG_BYTES_H;
        const __half* Ag = Ab + it * BKh;
        const __half* Bg = Bb + it * BKh;
        #pragma unroll
        for (int f = tid; f < 2048; f += 256) {
            int r = (f >> 3) & 127;
            int c = f & 7;
            const __half* src;
            uint32_t dst;
            if (f < 1024) {
                src = Ag + (size_t)r * K + c * 8;
                dst = stg + (uint32_t)(r * ROWB + c * 16);
            } else {
                src = Bg + (size_t)r * K + c * 8;
                dst = stg + (uint32_t)(128 * ROWB + r * ROWB + c * 16);
            }
            cp16(dst, src);
        }
        asm volatile("cp.async.commit_group;" ::: "memory");
    };

    float acc[4][4][4];
    #pragma unroll
    for (int i = 0; i < 4; i++)
        #pragma unroll
        for (int j = 0; j < 4; j++)
            #pragma unroll
            for (int t = 0; t < 4; t++) acc[i][j][t] = 0.f;

    issue(0);

    // ldmatrix lane address components
    const int a_row = lid & 15;                       // + wm + 16*mi
    const int a_kh  = (lid >> 4) << 3;                // k offset (halfs)
    const int b_row = ((lid >> 4) << 3) + (lid & 7);  // + wn + 16*bj
    const int b_kh  = ((lid >> 3) & 1) << 3;

    for (int it = 0; it < NIT; ++it) {
        if (it + 1 < NIT) {
            issue(it + 1);
            asm volatile("cp.async.wait_group 1;" ::: "memory");
        } else {
            asm volatile("cp.async.wait_group 0;" ::: "memory");
        }
        __syncthreads();

        uint32_t smA = sb + (uint32_t)(it & 1) * STG_BYTES_H;
        uint32_t smB = smA + 128 * ROWB;

        #pragma unroll
        for (int k16 = 0; k16 < BKh; k16 += 16) {
            uint32_t a[4][4], bf[2][4];
            #pragma unroll
            for (int mi = 0; mi < 4; mi++)
                ldsm_x4(a[mi], smA + (uint32_t)((wm + 16 * mi + a_row) * ROWB
                                                + (k16 + a_kh) * 2));
            #pragma unroll
            for (int bj = 0; bj < 2; bj++)
                ldsm_x4(bf[bj], smB + (uint32_t)((wn + 16 * bj + b_row) * ROWB
                                                 + (k16 + b_kh) * 2));
            #pragma unroll
            for (int mi = 0; mi < 4; mi++) {
                #pragma unroll
                for (int nj = 0; nj < 4; nj++) {
                    int bj = nj >> 1, hi = (nj & 1) << 1;
                    mma_f16(acc[mi][nj], a[mi], bf[bj][hi], bf[bj][hi + 1]);
                }
            }
        }
        __syncthreads();
    }

    // Epilogue
    const int g = lid >> 2, tg = lid & 3;
    #pragma unroll
    for (int mi = 0; mi < 4; mi++) {
        const int row0 = bm * BMh + wm + 16 * mi + g;
        #pragma unroll
        for (int nj = 0; nj < 4; nj++) {
            const int col = bn * BNh + wn + nj * 8 + 2 * tg;
            float bx = bias[col], by = bias[col + 1];
            float v0 = acc[mi][nj][0] + bx, v1 = acc[mi][nj][1] + by;
            float v2 = acc[mi][nj][2] + bx, v3 = acc[mi][nj][3] + by;
            if (Ch) {
                *(__half2*)(Ch + (size_t)row0 * N + col) = __floats2half2_rn(v0, v1);
                *(__half2*)(Ch + (size_t)(row0 + 8) * N + col) = __floats2half2_rn(v2, v3);
            } else {
                float2 r0 = *(const float2*)(res + (size_t)row0 * N + col);
                float2 r1 = *(const float2*)(res + (size_t)(row0 + 8) * N + col);
                float2 o0 = make_float2(v0 + r0.x, v1 + r0.y);
                float2 o1 = make_float2(v2 + r1.x, v3 + r1.y);
                *(float2*)(Cf + (size_t)row0 * N + col) = o0;
                *(float2*)(Cf + (size_t)(row0 + 8) * N + col) = o1;
            }
        }
    }
}

// ---------------------------------------------------------------------------
// Tensor-core windowed attention: one CTA per (b, h, window), 4 warps.
// QKV tiles loaded via cp.async (no register staging).
// ---------------------------------------------------------------------------
__global__ __launch_bounds__(128, 1)
void win_attn_tc(const __half* __restrict__ qkv, __half* __restrict__ outp)
{
    __shared__ __half Qs[64 * HSTR], Ks[64 * HSTR], Vs[64 * HSTR];

    const int tid = threadIdx.x, wid = tid >> 5, lid = tid & 31;
    const int w = blockIdx.x & 63;
    const int h = (blockIdx.x >> 6) & 15;
    const int b = blockIdx.x >> 10;

    const size_t base = ((size_t)(b * Lq + w * Wq)) * (3 * Dq) + h * HDq;
    const uint32_t qb = smem_u32(Qs), kb2_ = smem_u32(Ks), vb = smem_u32(Vs);

    // Async load Q, K, V tiles (64 rows x 64 halfs, padded rows of 72 halfs)
    #pragma unroll
    for (int f = tid; f < 512; f += 128) {
        int row = f >> 3;
        int cq = (f & 7) << 3;
        size_t gg = base + (size_t)row * (3 * Dq) + cq;
        uint32_t soff = (uint32_t)(row * ROWB + cq * 2);
        cp16(qb + soff, qkv + gg);
        cp16(kb2_ + soff, qkv + gg + Dq);
        cp16(vb + soff, qkv + gg + 2 * Dq);
    }
    asm volatile("cp.async.commit_group;" ::: "memory");
    asm volatile("cp.async.wait_group 0;" ::: "memory");
    __syncthreads();

    const int g = lid >> 2, tg = lid & 3;
    const int m0 = wid * 16;
    const int a_row = lid & 15;
    const int a_kh  = (lid >> 4) << 3;
    const int b_row = ((lid >> 4) << 3) + (lid & 7);
    const int b_kh  = ((lid >> 3) & 1) << 3;

    // Phase 1: S = Q K^T  (warp: m16 x n64 x k64)
    float accS[8][4];
    #pragma unroll
    for (int nj = 0; nj < 8; nj++)
        #pragma unroll
        for (int t = 0; t < 4; t++) accS[nj][t] = 0.f;

    #pragma unroll
    for (int kb = 0; kb < 4; kb++) {
        uint32_t a[4];
        ldsm_x4(a, qb + (uint32_t)((m0 + a_row) * ROWB + (kb * 16 + a_kh) * 2));
        #pragma unroll
        for (int bj = 0; bj < 4; bj++) {
            uint32_t bf[4];
            ldsm_x4(bf, kb2_ + (uint32_t)((16 * bj + b_row) * ROWB
                                          + (kb * 16 + b_kh) * 2));
            mma_f16(accS[2 * bj],     a, bf[0], bf[1]);
            mma_f16(accS[2 * bj + 1], a, bf[2], bf[3]);
        }
    }

    // Softmax in registers. Rows: ra = m0+g (c0,c1), rb = m0+g+8 (c2,c3).
    const float scale = 0.125f;
    float mxa = -1e30f, mxb = -1e30f;
    #pragma unroll
    for (int nj = 0; nj < 8; nj++) {
        #pragma unroll
        for (int t = 0; t < 4; t++) accS[nj][t] *= scale;
        mxa = fmaxf(mxa, fmaxf(accS[nj][0], accS[nj][1]));
        mxb = fmaxf(mxb, fmaxf(accS[nj][2], accS[nj][3]));
    }
    mxa = fmaxf(mxa, __shfl_xor_sync(0xffffffffu, mxa, 1));
    mxa = fmaxf(mxa, __shfl_xor_sync(0xffffffffu, mxa, 2));
    mxb = fmaxf(mxb, __shfl_xor_sync(0xffffffffu, mxb, 1));
    mxb = fmaxf(mxb, __shfl_xor_sync(0xffffffffu, mxb, 2));

    float suma = 0.f, sumb = 0.f;
    #pragma unroll
    for (int nj = 0; nj < 8; nj++) {
        accS[nj][0] = __expf(accS[nj][0] - mxa);
        accS[nj][1] = __expf(accS[nj][1] - mxa);
        accS[nj][2] = __expf(accS[nj][2] - mxb);
        accS[nj][3] = __expf(accS[nj][3] - mxb);
        suma += accS[nj][0] + accS[nj][1];
        sumb += accS[nj][2] + accS[nj][3];
    }
    suma += __shfl_xor_sync(0xffffffffu, suma, 1);
    suma += __shfl_xor_sync(0xffffffffu, suma, 2);
    sumb += __shfl_xor_sync(0xffffffffu, sumb, 1);
    sumb += __shfl_xor_sync(0xffffffffu, sumb, 2);
    const float inva = 1.f / suma, invb = 1.f / sumb;

    // Repack P into fp16 a-fragments
    uint32_t pa[4][4];
    #pragma unroll
    for (int kb2 = 0; kb2 < 4; kb2++) {
        pa[kb2][0] = h2u(accS[2 * kb2][0] * inva,     accS[2 * kb2][1] * inva);
        pa[kb2][1] = h2u(accS[2 * kb2][2] * invb,     accS[2 * kb2][3] * invb);
        pa[kb2][2] = h2u(accS[2 * kb2 + 1][0] * inva, accS[2 * kb2 + 1][1] * inva);
        pa[kb2][3] = h2u(accS[2 * kb2 + 1][2] * invb, accS[2 * kb2 + 1][3] * invb);
    }

    // Phase 2: O = P V
    float accO[8][4];
    #pragma unroll
    for (int nj = 0; nj < 8; nj++)
        #pragma unroll
        for (int t = 0; t < 4; t++) accO[nj][t] = 0.f;

    const int v_row = ((lid >> 3) & 1) * 8 + (lid & 7);   // + kb2*16
    const int v_col = ((lid >> 4) & 1) * 8;               // + 16*t

    #pragma unroll
    for (int kb2 = 0; kb2 < 4; kb2++) {
        #pragma unroll
        for (int t = 0; t < 4; t++) {
            uint32_t vf[4];
            ldsm_x4_t(vf, vb + (uint32_t)((kb2 * 16 + v_row) * ROWB
                                          + (16 * t + v_col) * 2));
            mma_f16(accO[2 * t],     pa[kb2], vf[0], vf[1]);
            mma_f16(accO[2 * t + 1], pa[kb2], vf[2], vf[3]);
        }
    }

    // Store O rows (fp16)
    const int orow = b * Lq + w * Wq + m0;
    #pragma unroll
    for (int nj = 0; nj < 8; nj++) {
        const int col = h * HDq + 8 * nj + 2 * tg;
        __half2 lo = __floats2half2_rn(accO[nj][0], accO[nj][1]);
        __half2 hi = __floats2half2_rn(accO[nj][2], accO[nj][3]);
        *(__half2*)(outp + (size_t)(orow + g) * Dq + col) = lo;
        *(__half2*)(outp + (size_t)(orow + g + 8) * Dq + col) = hi;
    }
}

// ---------------------------------------------------------------------------
// LayerNorm: one block per row (1024 elems, 256 threads x 4)
// ---------------------------------------------------------------------------
__global__ __launch_bounds__(256, 1)
void layernorm_k(const float* __restrict__ y, const float* __restrict__ gamma,
                 const float* __restrict__ beta, float* __restrict__ out)
{
    __shared__ float r1[8], r2[8];
    const int row = blockIdx.x;
    const int tid = threadIdx.x;
    const float* yr = y + (size_t)row * Dq;
    const int c = tid * 4;

    float4 v = *(const float4*)(yr + c);
    float s = v.x + v.y + v.z + v.w;
    #pragma unroll
    for (int o = 16; o; o >>= 1) s += __shfl_xor_sync(0xffffffffu, s, o);
    if ((tid & 31) == 0) r1[tid >> 5] = s;
    __syncthreads();

    float mean = 0.f;
    #pragma unroll
    for (int i = 0; i < 8; i++) mean += r1[i];
    mean *= (1.f / 1024.f);

    float dx = v.x - mean, dy = v.y - mean, dz = v.z - mean, dw = v.w - mean;
    float ss = dx * dx + dy * dy + dz * dz + dw * dw;
    #pragma unroll
    for (int o = 16; o; o >>= 1) ss += __shfl_xor_sync(0xffffffffu, ss, o);
    if ((tid & 31) == 0) r2[tid >> 5] = ss;
    __syncthreads();

    float var = 0.f;
    #pragma unroll
    for (int i = 0; i < 8; i++) var += r2[i];
    var *= (1.f / 1024.f);
    float inv = rsqrtf(var + 1e-5f);

    float4 gm = *(const float4*)(gamma + c);
    float4 bt = *(const float4*)(beta + c);
    float4 o4;
    o4.x = dx * inv * gm.x + bt.x;
    o4.y = dy * inv * gm.y + bt.y;
    o4.z = dz * inv * gm.z + bt.z;
    o4.w = dw * inv * gm.w + bt.w;
    *(float4*)(out + (size_t)row * Dq + c) = o4;
}

// ---------------------------------------------------------------------------
extern "C" void kernel_launch(void* const* d_in, const int* in_sizes, int n_in,
                              void* d_out, int out_size)
{
    const float* x     = (const float*)d_in[0];
    const float* Wqkv  = (const float*)d_in[1];
    const float* bqkv  = (const float*)d_in[2];
    const float* Wproj = (const float*)d_in[3];
    const float* bproj = (const float*)d_in[4];
    const float* gamma = (const float*)d_in[5];
    const float* beta  = (const float*)d_in[6];
    float* out = (float*)d_out;

    __half *xh, *wqkvh, *wprojh, *qkvh, *attnh;
    float* y;
    cudaGetSymbolAddress((void**)&xh,     g_xh);
    cudaGetSymbolAddress((void**)&wqkvh,  g_wqkvh);
    cudaGetSymbolAddress((void**)&wprojh, g_wprojh);
    cudaGetSymbolAddress((void**)&qkvh,   g_qkvh);
    cudaGetSymbolAddress((void**)&attnh,  g_attnh);
    cudaGetSymbolAddress((void**)&y,      g_y);

    cudaFuncSetAttribute(hgemm, cudaFuncAttributeMaxDynamicSharedMemorySize, GEMM_SMEM_H);

    // 0) fused fp32 -> fp16 conversions (x, Wqkv, Wproj)
    f2h_all<<<N_CVT / 2048, 256>>>(x, Wqkv, Wproj, xh, wqkvh, wprojh);

    // 1) QKV projection -> fp16 qkv
    hgemm<<<dim3(3 * Dq / BNh, Mrows / BMh), 256, GEMM_SMEM_H>>>(
        xh, wqkvh, bqkv, nullptr, qkvh, nullptr, 3 * Dq, Dq);
    // 2) Windowed attention (tensor cores) -> fp16 attn
    win_attn_tc<<<Bq * Hq * (Lq / Wq), 128>>>(qkvh, attnh);
    // 3) Output projection + bias + residual -> fp32 y
    hgemm<<<dim3(Dq / BNh, Mrows / BMh), 256, GEMM_SMEM_H>>>(
        attnh, wprojh, bproj, x, nullptr, y, Dq, Dq);
    // 4) LayerNorm -> out
    layernorm_k<<<Mrows, 256>>>(y, gamma, beta, out);
}

// round 15
// speedup vs baseline: 1.5644x; 1.0093x over previous
#include <cuda_runtime.h>
#include <cuda_fp16.h>
#include <math.h>
#include <stdint.h>

// Problem constants
#define Bq   4
#define Lq   4096
#define Dq   1024
#define Hq   16
#define Wq   64
#define HDq  64
#define Mrows (Bq*Lq)          // 16384

// Scratch buffers (device globals)
__device__ __half g_xh[(size_t)Mrows * Dq];          // 32 MB (reused as proj out)
__device__ __half g_wqkvh[(size_t)3 * Dq * Dq];      // 6 MB
__device__ __half g_wprojh[(size_t)Dq * Dq];         // 2 MB
__device__ __half g_qkvh[(size_t)Mrows * 3 * Dq];    // 96 MB
__device__ __half g_attnh[(size_t)Mrows * Dq];       // 32 MB

// ---------------------------------------------------------------------------
// Helpers
// ---------------------------------------------------------------------------
__device__ __forceinline__ uint32_t smem_u32(const void* p) {
    return (uint32_t)__cvta_generic_to_shared(p);
}
__device__ __forceinline__ void cp16(uint32_t s, const void* g) {
    asm volatile("cp.async.cg.shared.global [%0], [%1], 16;" :: "r"(s), "l"(g));
}
__device__ __forceinline__ void ldsm_x4(uint32_t r[4], uint32_t addr) {
    asm volatile("ldmatrix.sync.aligned.m8n8.x4.shared.b16 {%0,%1,%2,%3}, [%4];"
                 : "=r"(r[0]), "=r"(r[1]), "=r"(r[2]), "=r"(r[3]) : "r"(addr));
}
__device__ __forceinline__ void ldsm_x4_t(uint32_t r[4], uint32_t addr) {
    asm volatile("ldmatrix.sync.aligned.m8n8.x4.trans.shared.b16 {%0,%1,%2,%3}, [%4];"
                 : "=r"(r[0]), "=r"(r[1]), "=r"(r[2]), "=r"(r[3]) : "r"(addr));
}
__device__ __forceinline__ void mma_f16(float c[4], const uint32_t a[4],
                                        uint32_t b0, uint32_t b1) {
    asm volatile(
        "mma.sync.aligned.m16n8k16.row.col.f32.f16.f16.f32 "
        "{%0,%1,%2,%3}, {%4,%5,%6,%7}, {%8,%9}, {%0,%1,%2,%3};"
        : "+f"(c[0]), "+f"(c[1]), "+f"(c[2]), "+f"(c[3])
        : "r"(a[0]), "r"(a[1]), "r"(a[2]), "r"(a[3]), "r"(b0), "r"(b1));
}
__device__ __forceinline__ uint32_t h2u(float x, float y) {
    __half2 h = __floats2half2_rn(x, y);
    return *(uint32_t*)&h;
}

// ---------------------------------------------------------------------------
// Fused fp32 -> fp16 conversion for x, Wqkv, Wproj (one launch)
// ---------------------------------------------------------------------------
#define N_X   (Mrows * Dq)          // 16777216
#define N_WQ  (3 * Dq * Dq)         // 3145728
#define N_WP  (Dq * Dq)             // 1048576
#define N_CVT (N_X + N_WQ + N_WP)   // 20971520

__global__ __launch_bounds__(256, 1)
void f2h_all(const float* __restrict__ x, const float* __restrict__ wq,
             const float* __restrict__ wp, __half* __restrict__ xh,
             __half* __restrict__ wqh, __half* __restrict__ wph)
{
    int i = (blockIdx.x * 256 + threadIdx.x) * 8;
    const float* src;
    __half* dst;
    if (i < N_X)            { src = x + i;              dst = xh + i; }
    else if (i < N_X + N_WQ){ src = wq + (i - N_X);     dst = wqh + (i - N_X); }
    else                    { src = wp + (i - N_X - N_WQ); dst = wph + (i - N_X - N_WQ); }
    float4 v0 = *(const float4*)(src);
    float4 v1 = *(const float4*)(src + 4);
    __half2 h[4];
    h[0] = __floats2half2_rn(v0.x, v0.y);
    h[1] = __floats2half2_rn(v0.z, v0.w);
    h[2] = __floats2half2_rn(v1.x, v1.y);
    h[3] = __floats2half2_rn(v1.z, v1.w);
    *(uint4*)(dst) = *(uint4*)h;
}

// ---------------------------------------------------------------------------
// fp16 mma GEMM (NT): C[m][n] = sum_k A[m][k]*B[n][k] + bias[n], fp16 out.
// CTA 128x128x64(halfs), 256 thr (8 warps 2x4, 64x32 warp tiles), 2-stage
// cp.async ping-pong. SMEM rows padded to 72 halfs (144 B): ldmatrix
// conflict-free. (Best measured mainloop config.)
// ---------------------------------------------------------------------------
#define BMh 128
#define BNh 128
#define BKh 64
#define HSTR 72                                // halfs per padded row
#define ROWB (HSTR * 2)                        // 144 bytes per row
#define STG_BYTES_H (2 * 128 * ROWB)           // 36864 B per stage
#define GEMM_SMEM_H (2 * STG_BYTES_H)          // 73728 B

__global__ __launch_bounds__(256, 2)
void hgemm(const __half* __restrict__ A, const __half* __restrict__ B,
           const float* __restrict__ bias, __half* __restrict__ C,
           int N, int K)
{
    extern __shared__ __half hsm[];

    const int tid = threadIdx.x;
    const int wid = tid >> 5, lid = tid & 31;
    const int wm = (wid >> 2) * 64;
    const int wn = (wid & 3) * 32;

    const int bn = blockIdx.x, bm = blockIdx.y;
    const __half* Ab = A + (size_t)bm * BMh * K;
    const __half* Bb = B + (size_t)bn * BNh * K;
    const int NIT = K / BKh;                   // 16 for K=1024

    const uint32_t sb = smem_u32(hsm);

    auto issue = [&](int it) {
        uint32_t stg = sb + (uint32_t)(it & 1) * STG_BYTES_H;
        const __half* Ag = Ab + it * BKh;
        const __half* Bg = Bb + it * BKh;
        #pragma unroll
        for (int f = tid; f < 2048; f += 256) {
            int r = (f >> 3) & 127;
            int c = f & 7;
            const __half* src;
            uint32_t dst;
            if (f < 1024) {
                src = Ag + (size_t)r * K + c * 8;
                dst = stg + (uint32_t)(r * ROWB + c * 16);
            } else {
                src = Bg + (size_t)r * K + c * 8;
                dst = stg + (uint32_t)(128 * ROWB + r * ROWB + c * 16);
            }
            cp16(dst, src);
        }
        asm volatile("cp.async.commit_group;" ::: "memory");
    };

    float acc[4][4][4];
    #pragma unroll
    for (int i = 0; i < 4; i++)
        #pragma unroll
        for (int j = 0; j < 4; j++)
            #pragma unroll
            for (int t = 0; t < 4; t++) acc[i][j][t] = 0.f;

    issue(0);

    // ldmatrix lane address components
    const int a_row = lid & 15;                       // + wm + 16*mi
    const int a_kh  = (lid >> 4) << 3;                // k offset (halfs)
    const int b_row = ((lid >> 4) << 3) + (lid & 7);  // + wn + 16*bj
    const int b_kh  = ((lid >> 3) & 1) << 3;

    for (int it = 0; it < NIT; ++it) {
        if (it + 1 < NIT) {
            issue(it + 1);
            asm volatile("cp.async.wait_group 1;" ::: "memory");
        } else {
            asm volatile("cp.async.wait_group 0;" ::: "memory");
        }
        __syncthreads();

        uint32_t smA = sb + (uint32_t)(it & 1) * STG_BYTES_H;
        uint32_t smB = smA + 128 * ROWB;

        #pragma unroll
        for (int k16 = 0; k16 < BKh; k16 += 16) {
            uint32_t a[4][4], bf[2][4];
            #pragma unroll
            for (int mi = 0; mi < 4; mi++)
                ldsm_x4(a[mi], smA + (uint32_t)((wm + 16 * mi + a_row) * ROWB
                                                + (k16 + a_kh) * 2));
            #pragma unroll
            for (int bj = 0; bj < 2; bj++)
                ldsm_x4(bf[bj], smB + (uint32_t)((wn + 16 * bj + b_row) * ROWB
                                                 + (k16 + b_kh) * 2));
            #pragma unroll
            for (int mi = 0; mi < 4; mi++) {
                #pragma unroll
                for (int nj = 0; nj < 4; nj++) {
                    int bj = nj >> 1, hi = (nj & 1) << 1;
                    mma_f16(acc[mi][nj], a[mi], bf[bj][hi], bf[bj][hi + 1]);
                }
            }
        }
        __syncthreads();
    }

    // Epilogue: bias add, fp16 stores
    const int g = lid >> 2, tg = lid & 3;
    #pragma unroll
    for (int mi = 0; mi < 4; mi++) {
        const int row0 = bm * BMh + wm + 16 * mi + g;
        #pragma unroll
        for (int nj = 0; nj < 4; nj++) {
            const int col = bn * BNh + wn + nj * 8 + 2 * tg;
            float bx = bias[col], by = bias[col + 1];
            *(__half2*)(C + (size_t)row0 * N + col) =
                __floats2half2_rn(acc[mi][nj][0] + bx, acc[mi][nj][1] + by);
            *(__half2*)(C + (size_t)(row0 + 8) * N + col) =
                __floats2half2_rn(acc[mi][nj][2] + bx, acc[mi][nj][3] + by);
        }
    }
}

// ---------------------------------------------------------------------------
// Tensor-core windowed attention: one CTA per (b, h, window), 4 warps.
// ---------------------------------------------------------------------------
__global__ __launch_bounds__(128, 1)
void win_attn_tc(const __half* __restrict__ qkv, __half* __restrict__ outp)
{
    __shared__ __half Qs[64 * HSTR], Ks[64 * HSTR], Vs[64 * HSTR];

    const int tid = threadIdx.x, wid = tid >> 5, lid = tid & 31;
    const int w = blockIdx.x & 63;
    const int h = (blockIdx.x >> 6) & 15;
    const int b = blockIdx.x >> 10;

    const size_t base = ((size_t)(b * Lq + w * Wq)) * (3 * Dq) + h * HDq;
    const uint32_t qb = smem_u32(Qs), kb2_ = smem_u32(Ks), vb = smem_u32(Vs);

    // Async load Q, K, V tiles (64 rows x 64 halfs, padded rows of 72 halfs)
    #pragma unroll
    for (int f = tid; f < 512; f += 128) {
        int row = f >> 3;
        int cq = (f & 7) << 3;
        size_t gg = base + (size_t)row * (3 * Dq) + cq;
        uint32_t soff = (uint32_t)(row * ROWB + cq * 2);
        cp16(qb + soff, qkv + gg);
        cp16(kb2_ + soff, qkv + gg + Dq);
        cp16(vb + soff, qkv + gg + 2 * Dq);
    }
    asm volatile("cp.async.commit_group;" ::: "memory");
    asm volatile("cp.async.wait_group 0;" ::: "memory");
    __syncthreads();

    const int g = lid >> 2, tg = lid & 3;
    const int m0 = wid * 16;
    const int a_row = lid & 15;
    const int a_kh  = (lid >> 4) << 3;
    const int b_row = ((lid >> 4) << 3) + (lid & 7);
    const int b_kh  = ((lid >> 3) & 1) << 3;

    // Phase 1: S = Q K^T  (warp: m16 x n64 x k64)
    float accS[8][4];
    #pragma unroll
    for (int nj = 0; nj < 8; nj++)
        #pragma unroll
        for (int t = 0; t < 4; t++) accS[nj][t] = 0.f;

    #pragma unroll
    for (int kb = 0; kb < 4; kb++) {
        uint32_t a[4];
        ldsm_x4(a, qb + (uint32_t)((m0 + a_row) * ROWB + (kb * 16 + a_kh) * 2));
        #pragma unroll
        for (int bj = 0; bj < 4; bj++) {
            uint32_t bf[4];
            ldsm_x4(bf, kb2_ + (uint32_t)((16 * bj + b_row) * ROWB
                                          + (kb * 16 + b_kh) * 2));
            mma_f16(accS[2 * bj],     a, bf[0], bf[1]);
            mma_f16(accS[2 * bj + 1], a, bf[2], bf[3]);
        }
    }

    // Softmax in registers. Rows: ra = m0+g (c0,c1), rb = m0+g+8 (c2,c3).
    const float scale = 0.125f;
    float mxa = -1e30f, mxb = -1e30f;
    #pragma unroll
    for (int nj = 0; nj < 8; nj++) {
        #pragma unroll
        for (int t = 0; t < 4; t++) accS[nj][t] *= scale;
        mxa = fmaxf(mxa, fmaxf(accS[nj][0], accS[nj][1]));
        mxb = fmaxf(mxb, fmaxf(accS[nj][2], accS[nj][3]));
    }
    mxa = fmaxf(mxa, __shfl_xor_sync(0xffffffffu, mxa, 1));
    mxa = fmaxf(mxa, __shfl_xor_sync(0xffffffffu, mxa, 2));
    mxb = fmaxf(mxb, __shfl_xor_sync(0xffffffffu, mxb, 1));
    mxb = fmaxf(mxb, __shfl_xor_sync(0xffffffffu, mxb, 2));

    float suma = 0.f, sumb = 0.f;
    #pragma unroll
    for (int nj = 0; nj < 8; nj++) {
        accS[nj][0] = __expf(accS[nj][0] - mxa);
        accS[nj][1] = __expf(accS[nj][1] - mxa);
        accS[nj][2] = __expf(accS[nj][2] - mxb);
        accS[nj][3] = __expf(accS[nj][3] - mxb);
        suma += accS[nj][0] + accS[nj][1];
        sumb += accS[nj][2] + accS[nj][3];
    }
    suma += __shfl_xor_sync(0xffffffffu, suma, 1);
    suma += __shfl_xor_sync(0xffffffffu, suma, 2);
    sumb += __shfl_xor_sync(0xffffffffu, sumb, 1);
    sumb += __shfl_xor_sync(0xffffffffu, sumb, 2);
    const float inva = 1.f / suma, invb = 1.f / sumb;

    // Repack P into fp16 a-fragments
    uint32_t pa[4][4];
    #pragma unroll
    for (int kb2 = 0; kb2 < 4; kb2++) {
        pa[kb2][0] = h2u(accS[2 * kb2][0] * inva,     accS[2 * kb2][1] * inva);
        pa[kb2][1] = h2u(accS[2 * kb2][2] * invb,     accS[2 * kb2][3] * invb);
        pa[kb2][2] = h2u(accS[2 * kb2 + 1][0] * inva, accS[2 * kb2 + 1][1] * inva);
        pa[kb2][3] = h2u(accS[2 * kb2 + 1][2] * invb, accS[2 * kb2 + 1][3] * invb);
    }

    // Phase 2: O = P V
    float accO[8][4];
    #pragma unroll
    for (int nj = 0; nj < 8; nj++)
        #pragma unroll
        for (int t = 0; t < 4; t++) accO[nj][t] = 0.f;

    const int v_row = ((lid >> 3) & 1) * 8 + (lid & 7);   // + kb2*16
    const int v_col = ((lid >> 4) & 1) * 8;               // + 16*t

    #pragma unroll
    for (int kb2 = 0; kb2 < 4; kb2++) {
        #pragma unroll
        for (int t = 0; t < 4; t++) {
            uint32_t vf[4];
            ldsm_x4_t(vf, vb + (uint32_t)((kb2 * 16 + v_row) * ROWB
                                          + (16 * t + v_col) * 2));
            mma_f16(accO[2 * t],     pa[kb2], vf[0], vf[1]);
            mma_f16(accO[2 * t + 1], pa[kb2], vf[2], vf[3]);
        }
    }

    // Store O rows (fp16)
    const int orow = b * Lq + w * Wq + m0;
    #pragma unroll
    for (int nj = 0; nj < 8; nj++) {
        const int col = h * HDq + 8 * nj + 2 * tg;
        __half2 lo = __floats2half2_rn(accO[nj][0], accO[nj][1]);
        __half2 hi = __floats2half2_rn(accO[nj][2], accO[nj][3]);
        *(__half2*)(outp + (size_t)(orow + g) * Dq + col) = lo;
        *(__half2*)(outp + (size_t)(orow + g + 8) * Dq + col) = hi;
    }
}

// ---------------------------------------------------------------------------
// Fused residual + LayerNorm: y = proj(fp16) + x(fp32); out = LN(y)*g + b.
// One block per row, 256 threads x 4 elems.
// ---------------------------------------------------------------------------
__global__ __launch_bounds__(256, 1)
void res_ln_k(const __half* __restrict__ proj, const float* __restrict__ x,
              const float* __restrict__ gamma, const float* __restrict__ beta,
              float* __restrict__ out)
{
    __shared__ float r1[8], r2[8];
    const int row = blockIdx.x;
    const int tid = threadIdx.x;
    const int c = tid * 4;

    // y = proj + x (fp32 math)
    uint2 ph = *(const uint2*)(proj + (size_t)row * Dq + c);
    float2 p0 = __half22float2(*(__half2*)&ph.x);
    float2 p1 = __half22float2(*(__half2*)&ph.y);
    float4 xv = *(const float4*)(x + (size_t)row * Dq + c);
    float4 v;
    v.x = p0.x + xv.x; v.y = p0.y + xv.y;
    v.z = p1.x + xv.z; v.w = p1.y + xv.w;

    float s = v.x + v.y + v.z + v.w;
    #pragma unroll
    for (int o = 16; o; o >>= 1) s += __shfl_xor_sync(0xffffffffu, s, o);
    if ((tid & 31) == 0) r1[tid >> 5] = s;
    __syncthreads();

    float mean = 0.f;
    #pragma unroll
    for (int i = 0; i < 8; i++) mean += r1[i];
    mean *= (1.f / 1024.f);

    float dx = v.x - mean, dy = v.y - mean, dz = v.z - mean, dw = v.w - mean;
    float ss = dx * dx + dy * dy + dz * dz + dw * dw;
    #pragma unroll
    for (int o = 16; o; o >>= 1) ss += __shfl_xor_sync(0xffffffffu, ss, o);
    if ((tid & 31) == 0) r2[tid >> 5] = ss;
    __syncthreads();

    float var = 0.f;
    #pragma unroll
    for (int i = 0; i < 8; i++) var += r2[i];
    var *= (1.f / 1024.f);
    float inv = rsqrtf(var + 1e-5f);

    float4 gm = *(const float4*)(gamma + c);
    float4 bt = *(const float4*)(beta + c);
    float4 o4;
    o4.x = dx * inv * gm.x + bt.x;
    o4.y = dy * inv * gm.y + bt.y;
    o4.z = dz * inv * gm.z + bt.z;
    o4.w = dw * inv * gm.w + bt.w;
    *(float4*)(out + (size_t)row * Dq + c) = o4;
}

// ---------------------------------------------------------------------------
extern "C" void kernel_launch(void* const* d_in, const int* in_sizes, int n_in,
                              void* d_out, int out_size)
{
    const float* x     = (const float*)d_in[0];
    const float* Wqkv  = (const float*)d_in[1];
    const float* bqkv  = (const float*)d_in[2];
    const float* Wproj = (const float*)d_in[3];
    const float* bproj = (const float*)d_in[4];
    const float* gamma = (const float*)d_in[5];
    const float* beta  = (const float*)d_in[6];
    float* out = (float*)d_out;

    __half *xh, *wqkvh, *wprojh, *qkvh, *attnh;
    cudaGetSymbolAddress((void**)&xh,     g_xh);
    cudaGetSymbolAddress((void**)&wqkvh,  g_wqkvh);
    cudaGetSymbolAddress((void**)&wprojh, g_wprojh);
    cudaGetSymbolAddress((void**)&qkvh,   g_qkvh);
    cudaGetSymbolAddress((void**)&attnh,  g_attnh);
    __half* projh = xh;   // g_xh is dead after GEMM1; reuse for proj output

    cudaFuncSetAttribute(hgemm, cudaFuncAttributeMaxDynamicSharedMemorySize, GEMM_SMEM_H);

    // 0) fused fp32 -> fp16 conversions (x, Wqkv, Wproj)
    f2h_all<<<N_CVT / 2048, 256>>>(x, Wqkv, Wproj, xh, wqkvh, wprojh);

    // 1) QKV projection -> fp16 qkv
    hgemm<<<dim3(3 * Dq / BNh, Mrows / BMh), 256, GEMM_SMEM_H>>>(
        xh, wqkvh, bqkv, qkvh, 3 * Dq, Dq);
    // 2) Windowed attention (tensor cores) -> fp16 attn
    win_attn_tc<<<Bq * Hq * (Lq / Wq), 128>>>(qkvh, attnh);
    // 3) Output projection + bias -> fp16 proj (reuses g_xh)
    hgemm<<<dim3(Dq / BNh, Mrows / BMh), 256, GEMM_SMEM_H>>>(
        attnh, wprojh, bproj, projh, Dq, Dq);
    // 4) Residual + LayerNorm -> out
    res_ln_k<<<Mrows, 256>>>(projh, x, gamma, beta, out);
}

// round 17
// speedup vs baseline: 1.5746x; 1.0065x over previous
#include <cuda_runtime.h>
#include <cuda_fp16.h>
#include <math.h>
#include <stdint.h>

// Problem constants
#define Bq   4
#define Lq   4096
#define Dq   1024
#define Hq   16
#define Wq   64
#define HDq  64
#define Mrows (Bq*Lq)          // 16384

// Scratch buffers (device globals)
__device__ __half g_xh[(size_t)Mrows * Dq];          // 32 MB
__device__ __half g_wqkvh[(size_t)3 * Dq * Dq];      // 6 MB
__device__ __half g_wprojh[(size_t)Dq * Dq];         // 2 MB
__device__ __half g_qkvh[(size_t)Mrows * 3 * Dq];    // 96 MB
__device__ __half g_attnh[(size_t)Mrows * Dq];       // 32 MB
__device__ __half g_projh[(size_t)Mrows * Dq];       // 32 MB

// ---------------------------------------------------------------------------
// Helpers
// ---------------------------------------------------------------------------
__device__ __forceinline__ uint32_t smem_u32(const void* p) {
    return (uint32_t)__cvta_generic_to_shared(p);
}
__device__ __forceinline__ void cp16(uint32_t s, const void* g) {
    asm volatile("cp.async.cg.shared.global [%0], [%1], 16;" :: "r"(s), "l"(g));
}
__device__ __forceinline__ void ldsm_x4(uint32_t r[4], uint32_t addr) {
    asm volatile("ldmatrix.sync.aligned.m8n8.x4.shared.b16 {%0,%1,%2,%3}, [%4];"
                 : "=r"(r[0]), "=r"(r[1]), "=r"(r[2]), "=r"(r[3]) : "r"(addr));
}
__device__ __forceinline__ void ldsm_x4_t(uint32_t r[4], uint32_t addr) {
    asm volatile("ldmatrix.sync.aligned.m8n8.x4.trans.shared.b16 {%0,%1,%2,%3}, [%4];"
                 : "=r"(r[0]), "=r"(r[1]), "=r"(r[2]), "=r"(r[3]) : "r"(addr));
}
__device__ __forceinline__ void mma_f16(float c[4], const uint32_t a[4],
                                        uint32_t b0, uint32_t b1) {
    asm volatile(
        "mma.sync.aligned.m16n8k16.row.col.f32.f16.f16.f32 "
        "{%0,%1,%2,%3}, {%4,%5,%6,%7}, {%8,%9}, {%0,%1,%2,%3};"
        : "+f"(c[0]), "+f"(c[1]), "+f"(c[2]), "+f"(c[3])
        : "r"(a[0]), "r"(a[1]), "r"(a[2]), "r"(a[3]), "r"(b0), "r"(b1));
}
__device__ __forceinline__ uint32_t h2u(float x, float y) {
    __half2 h = __floats2half2_rn(x, y);
    return *(uint32_t*)&h;
}

// ---------------------------------------------------------------------------
// Fused fp32 -> fp16 conversion for x, Wqkv, Wproj (one launch)
// ---------------------------------------------------------------------------
#define N_X   (Mrows * Dq)          // 16777216
#define N_WQ  (3 * Dq * Dq)         // 3145728
#define N_WP  (Dq * Dq)             // 1048576
#define N_CVT (N_X + N_WQ + N_WP)   // 20971520

__global__ __launch_bounds__(256, 1)
void f2h_all(const float* __restrict__ x, const float* __restrict__ wq,
             const float* __restrict__ wp, __half* __restrict__ xh,
             __half* __restrict__ wqh, __half* __restrict__ wph)
{
    int i = (blockIdx.x * 256 + threadIdx.x) * 8;
    const float* src;
    __half* dst;
    if (i < N_X)            { src = x + i;              dst = xh + i; }
    else if (i < N_X + N_WQ){ src = wq + (i - N_X);     dst = wqh + (i - N_X); }
    else                    { src = wp + (i - N_X - N_WQ); dst = wph + (i - N_X - N_WQ); }
    float4 v0 = *(const float4*)(src);
    float4 v1 = *(const float4*)(src + 4);
    __half2 h[4];
    h[0] = __floats2half2_rn(v0.x, v0.y);
    h[1] = __floats2half2_rn(v0.z, v0.w);
    h[2] = __floats2half2_rn(v1.x, v1.y);
    h[3] = __floats2half2_rn(v1.z, v1.w);
    *(uint4*)(dst) = *(uint4*)h;
}

// ---------------------------------------------------------------------------
// fp16 mma GEMM (NT): C[m][n] = sum_k A[m][k]*B[n][k] + bias[n], fp16 out.
// CTA 128x128x64(halfs), 256 thr (8 warps 2x4, 64x32 warp tiles), 2-stage
// cp.async ping-pong. SMEM rows padded to 72 halfs (144 B). Proven mainloop.
// ---------------------------------------------------------------------------
#define BMh 128
#define BNh 128
#define BKh 64
#define HSTR 72                                // halfs per padded row
#define ROWB (HSTR * 2)                        // 144 bytes per row
#define STG_BYTES_H (2 * 128 * ROWB)           // 36864 B per stage
#define GEMM_SMEM_H (2 * STG_BYTES_H)          // 73728 B

__global__ __launch_bounds__(256, 2)
void hgemm(const __half* __restrict__ A, const __half* __restrict__ B,
           const float* __restrict__ bias, __half* __restrict__ C,
           int N, int K)
{
    extern __shared__ __half hsm[];

    const int tid = threadIdx.x;
    const int wid = tid >> 5, lid = tid & 31;
    const int wm = (wid >> 2) * 64;
    const int wn = (wid & 3) * 32;

    const int bn = blockIdx.x, bm = blockIdx.y;
    const __half* Ab = A + (size_t)bm * BMh * K;
    const __half* Bb = B + (size_t)bn * BNh * K;
    const int NIT = K / BKh;                   // 16 for K=1024

    const uint32_t sb = smem_u32(hsm);

    auto issue = [&](int it) {
        uint32_t stg = sb + (uint32_t)(it & 1) * STG_BYTES_H;
        const __half* Ag = Ab + it * BKh;
        const __half* Bg = Bb + it * BKh;
        #pragma unroll
        for (int f = tid; f < 2048; f += 256) {
            int r = (f >> 3) & 127;
            int c = f & 7;
            const __half* src;
            uint32_t dst;
            if (f < 1024) {
                src = Ag + (size_t)r * K + c * 8;
                dst = stg + (uint32_t)(r * ROWB + c * 16);
            } else {
                src = Bg + (size_t)r * K + c * 8;
                dst = stg + (uint32_t)(128 * ROWB + r * ROWB + c * 16);
            }
            cp16(dst, src);
        }
        asm volatile("cp.async.commit_group;" ::: "memory");
    };

    float acc[4][4][4];
    #pragma unroll
    for (int i = 0; i < 4; i++)
        #pragma unroll
        for (int j = 0; j < 4; j++)
            #pragma unroll
            for (int t = 0; t < 4; t++) acc[i][j][t] = 0.f;

    issue(0);

    const int a_row = lid & 15;
    const int a_kh  = (lid >> 4) << 3;
    const int b_row = ((lid >> 4) << 3) + (lid & 7);
    const int b_kh  = ((lid >> 3) & 1) << 3;

    for (int it = 0; it < NIT; ++it) {
        if (it + 1 < NIT) {
            issue(it + 1);
            asm volatile("cp.async.wait_group 1;" ::: "memory");
        } else {
            asm volatile("cp.async.wait_group 0;" ::: "memory");
        }
        __syncthreads();

        uint32_t smA = sb + (uint32_t)(it & 1) * STG_BYTES_H;
        uint32_t smB = smA + 128 * ROWB;

        #pragma unroll
        for (int k16 = 0; k16 < BKh; k16 += 16) {
            uint32_t a[4][4], bf[2][4];
            #pragma unroll
            for (int mi = 0; mi < 4; mi++)
                ldsm_x4(a[mi], smA + (uint32_t)((wm + 16 * mi + a_row) * ROWB
                                                + (k16 + a_kh) * 2));
            #pragma unroll
            for (int bj = 0; bj < 2; bj++)
                ldsm_x4(bf[bj], smB + (uint32_t)((wn + 16 * bj + b_row) * ROWB
                                                 + (k16 + b_kh) * 2));
            #pragma unroll
            for (int mi = 0; mi < 4; mi++) {
                #pragma unroll
                for (int nj = 0; nj < 4; nj++) {
                    int bj = nj >> 1, hi = (nj & 1) << 1;
                    mma_f16(acc[mi][nj], a[mi], bf[bj][hi], bf[bj][hi + 1]);
                }
            }
        }
        __syncthreads();
    }

    // Epilogue: bias add, fp16 stores
    const int g = lid >> 2, tg = lid & 3;
    #pragma unroll
    for (int mi = 0; mi < 4; mi++) {
        const int row0 = bm * BMh + wm + 16 * mi + g;
        #pragma unroll
        for (int nj = 0; nj < 4; nj++) {
            const int col = bn * BNh + wn + nj * 8 + 2 * tg;
            float bx = bias[col], by = bias[col + 1];
            *(__half2*)(C + (size_t)row0 * N + col) =
                __floats2half2_rn(acc[mi][nj][0] + bx, acc[mi][nj][1] + by);
            *(__half2*)(C + (size_t)(row0 + 8) * N + col) =
                __floats2half2_rn(acc[mi][nj][2] + bx, acc[mi][nj][3] + by);
        }
    }
}

// ---------------------------------------------------------------------------
// Tensor-core windowed attention, 4 windows per CTA with 2-stage cp.async
// double buffering. 4 warps; warp w owns S/O rows [16w,16w+16) of the
// current window. Fragment math identical to the proven single-window kernel.
// ---------------------------------------------------------------------------
#define UPC 4                                   // windows (units) per CTA
#define ATT_TILE (64 * HSTR)                    // halfs per Q/K/V tile

__global__ __launch_bounds__(128, 3)
void win_attn_tc(const __half* __restrict__ qkv, __half* __restrict__ outp)
{
    __shared__ __half St[2][3][ATT_TILE];       // [stage][Q,K,V][tile]

    const int tid = threadIdx.x, wid = tid >> 5, lid = tid & 31;
    const int u0 = blockIdx.x * UPC;

    // async loader for unit u into stage s
    auto issue = [&](int u, int s) {
        const int w = u & 63, h = (u >> 6) & 15, b = u >> 10;
        const size_t base = ((size_t)(b * Lq + w * Wq)) * (3 * Dq) + h * HDq;
        const uint32_t qd = smem_u32(St[s][0]);
        const uint32_t kd = smem_u32(St[s][1]);
        const uint32_t vd = smem_u32(St[s][2]);
        #pragma unroll
        for (int f = tid; f < 512; f += 128) {
            int row = f >> 3;
            int cq = (f & 7) << 3;
            size_t gg = base + (size_t)row * (3 * Dq) + cq;
            uint32_t soff = (uint32_t)(row * ROWB + cq * 2);
            cp16(qd + soff, qkv + gg);
            cp16(kd + soff, qkv + gg + Dq);
            cp16(vd + soff, qkv + gg + 2 * Dq);
        }
        asm volatile("cp.async.commit_group;" ::: "memory");
    };

    issue(u0, 0);

    const int g = lid >> 2, tg = lid & 3;
    const int m0 = wid * 16;
    const int a_row = lid & 15;
    const int a_kh  = (lid >> 4) << 3;
    const int b_row = ((lid >> 4) << 3) + (lid & 7);
    const int b_kh  = ((lid >> 3) & 1) << 3;
    const int v_row = ((lid >> 3) & 1) * 8 + (lid & 7);
    const int v_col = ((lid >> 4) & 1) * 8;

    for (int j = 0; j < UPC; ++j) {
        if (j + 1 < UPC) {
            issue(u0 + j + 1, (j + 1) & 1);
            asm volatile("cp.async.wait_group 1;" ::: "memory");
        } else {
            asm volatile("cp.async.wait_group 0;" ::: "memory");
        }
        __syncthreads();

        const int s = j & 1;
        const uint32_t qb   = smem_u32(St[s][0]);
        const uint32_t kb2_ = smem_u32(St[s][1]);
        const uint32_t vb   = smem_u32(St[s][2]);

        // Phase 1: S = Q K^T  (warp: m16 x n64 x k64)
        float accS[8][4];
        #pragma unroll
        for (int nj = 0; nj < 8; nj++)
            #pragma unroll
            for (int t = 0; t < 4; t++) accS[nj][t] = 0.f;

        #pragma unroll
        for (int kb = 0; kb < 4; kb++) {
            uint32_t a[4];
            ldsm_x4(a, qb + (uint32_t)((m0 + a_row) * ROWB + (kb * 16 + a_kh) * 2));
            #pragma unroll
            for (int bj = 0; bj < 4; bj++) {
                uint32_t bf[4];
                ldsm_x4(bf, kb2_ + (uint32_t)((16 * bj + b_row) * ROWB
                                              + (kb * 16 + b_kh) * 2));
                mma_f16(accS[2 * bj],     a, bf[0], bf[1]);
                mma_f16(accS[2 * bj + 1], a, bf[2], bf[3]);
            }
        }

        // Softmax in registers
        const float scale = 0.125f;
        float mxa = -1e30f, mxb = -1e30f;
        #pragma unroll
        for (int nj = 0; nj < 8; nj++) {
            #pragma unroll
            for (int t = 0; t < 4; t++) accS[nj][t] *= scale;
            mxa = fmaxf(mxa, fmaxf(accS[nj][0], accS[nj][1]));
            mxb = fmaxf(mxb, fmaxf(accS[nj][2], accS[nj][3]));
        }
        mxa = fmaxf(mxa, __shfl_xor_sync(0xffffffffu, mxa, 1));
        mxa = fmaxf(mxa, __shfl_xor_sync(0xffffffffu, mxa, 2));
        mxb = fmaxf(mxb, __shfl_xor_sync(0xffffffffu, mxb, 1));
        mxb = fmaxf(mxb, __shfl_xor_sync(0xffffffffu, mxb, 2));

        float suma = 0.f, sumb = 0.f;
        #pragma unroll
        for (int nj = 0; nj < 8; nj++) {
            accS[nj][0] = __expf(accS[nj][0] - mxa);
            accS[nj][1] = __expf(accS[nj][1] - mxa);
            accS[nj][2] = __expf(accS[nj][2] - mxb);
            accS[nj][3] = __expf(accS[nj][3] - mxb);
            suma += accS[nj][0] + accS[nj][1];
            sumb += accS[nj][2] + accS[nj][3];
        }
        suma += __shfl_xor_sync(0xffffffffu, suma, 1);
        suma += __shfl_xor_sync(0xffffffffu, suma, 2);
        sumb += __shfl_xor_sync(0xffffffffu, sumb, 1);
        sumb += __shfl_xor_sync(0xffffffffu, sumb, 2);
        const float inva = 1.f / suma, invb = 1.f / sumb;

        // Repack P into fp16 a-fragments
        uint32_t pa[4][4];
        #pragma unroll
        for (int kb2 = 0; kb2 < 4; kb2++) {
            pa[kb2][0] = h2u(accS[2 * kb2][0] * inva,     accS[2 * kb2][1] * inva);
            pa[kb2][1] = h2u(accS[2 * kb2][2] * invb,     accS[2 * kb2][3] * invb);
            pa[kb2][2] = h2u(accS[2 * kb2 + 1][0] * inva, accS[2 * kb2 + 1][1] * inva);
            pa[kb2][3] = h2u(accS[2 * kb2 + 1][2] * invb, accS[2 * kb2 + 1][3] * invb);
        }

        // Phase 2: O = P V
        float accO[8][4];
        #pragma unroll
        for (int nj = 0; nj < 8; nj++)
            #pragma unroll
            for (int t = 0; t < 4; t++) accO[nj][t] = 0.f;

        #pragma unroll
        for (int kb2 = 0; kb2 < 4; kb2++) {
            #pragma unroll
            for (int t = 0; t < 4; t++) {
                uint32_t vf[4];
                ldsm_x4_t(vf, vb + (uint32_t)((kb2 * 16 + v_row) * ROWB
                                              + (16 * t + v_col) * 2));
                mma_f16(accO[2 * t],     pa[kb2], vf[0], vf[1]);
                mma_f16(accO[2 * t + 1], pa[kb2], vf[2], vf[3]);
            }
        }

        // Store O rows (fp16)
        const int u = u0 + j;
        const int w = u & 63, h = (u >> 6) & 15, b = u >> 10;
        const int orow = b * Lq + w * Wq + m0;
        #pragma unroll
        for (int nj = 0; nj < 8; nj++) {
            const int col = h * HDq + 8 * nj + 2 * tg;
            __half2 lo = __floats2half2_rn(accO[nj][0], accO[nj][1]);
            __half2 hi = __floats2half2_rn(accO[nj][2], accO[nj][3]);
            *(__half2*)(outp + (size_t)(orow + g) * Dq + col) = lo;
            *(__half2*)(outp + (size_t)(orow + g + 8) * Dq + col) = hi;
        }
        __syncthreads();   // protect stage (j&1) before it is refilled
    }
}

// ---------------------------------------------------------------------------
// Fused residual + LayerNorm: y = proj(fp16) + x(fp16); out = LN(y)*g + b.
// One block per row, 256 threads x 4 elems.
// ---------------------------------------------------------------------------
__global__ __launch_bounds__(256, 1)
void res_ln_k(const __half* __restrict__ proj, const __half* __restrict__ xh,
              const float* __restrict__ gamma, const float* __restrict__ beta,
              float* __restrict__ out)
{
    __shared__ float r1[8], r2[8];
    const int row = blockIdx.x;
    const int tid = threadIdx.x;
    const int c = tid * 4;

    uint2 ph = *(const uint2*)(proj + (size_t)row * Dq + c);
    uint2 xh2 = *(const uint2*)(xh + (size_t)row * Dq + c);
    float2 p0 = __half22float2(*(__half2*)&ph.x);
    float2 p1 = __half22float2(*(__half2*)&ph.y);
    float2 x0 = __half22float2(*(__half2*)&xh2.x);
    float2 x1 = __half22float2(*(__half2*)&xh2.y);
    float4 v;
    v.x = p0.x + x0.x; v.y = p0.y + x0.y;
    v.z = p1.x + x1.x; v.w = p1.y + x1.y;

    float s = v.x + v.y + v.z + v.w;
    #pragma unroll
    for (int o = 16; o; o >>= 1) s += __shfl_xor_sync(0xffffffffu, s, o);
    if ((tid & 31) == 0) r1[tid >> 5] = s;
    __syncthreads();

    float mean = 0.f;
    #pragma unroll
    for (int i = 0; i < 8; i++) mean += r1[i];
    mean *= (1.f / 1024.f);

    float dx = v.x - mean, dy = v.y - mean, dz = v.z - mean, dw = v.w - mean;
    float ss = dx * dx + dy * dy + dz * dz + dw * dw;
    #pragma unroll
    for (int o = 16; o; o >>= 1) ss += __shfl_xor_sync(0xffffffffu, ss, o);
    if ((tid & 31) == 0) r2[tid >> 5] = ss;
    __syncthreads();

    float var = 0.f;
    #pragma unroll
    for (int i = 0; i < 8; i++) var += r2[i];
    var *= (1.f / 1024.f);
    float inv = rsqrtf(var + 1e-5f);

    float4 gm = *(const float4*)(gamma + c);
    float4 bt = *(const float4*)(beta + c);
    float4 o4;
    o4.x = dx * inv * gm.x + bt.x;
    o4.y = dy * inv * gm.y + bt.y;
    o4.z = dz * inv * gm.z + bt.z;
    o4.w = dw * inv * gm.w + bt.w;
    *(float4*)(out + (size_t)row * Dq + c) = o4;
}

// ---------------------------------------------------------------------------
extern "C" void kernel_launch(void* const* d_in, const int* in_sizes, int n_in,
                              void* d_out, int out_size)
{
    const float* x     = (const float*)d_in[0];
    const float* Wqkv  = (const float*)d_in[1];
    const float* bqkv  = (const float*)d_in[2];
    const float* Wproj = (const float*)d_in[3];
    const float* bproj = (const float*)d_in[4];
    const float* gamma = (const float*)d_in[5];
    const float* beta  = (const float*)d_in[6];
    float* out = (float*)d_out;

    __half *xh, *wqkvh, *wprojh, *qkvh, *attnh, *projh;
    cudaGetSymbolAddress((void**)&xh,     g_xh);
    cudaGetSymbolAddress((void**)&wqkvh,  g_wqkvh);
    cudaGetSymbolAddress((void**)&wprojh, g_wprojh);
    cudaGetSymbolAddress((void**)&qkvh,   g_qkvh);
    cudaGetSymbolAddress((void**)&attnh,  g_attnh);
    cudaGetSymbolAddress((void**)&projh,  g_projh);

    cudaFuncSetAttribute(hgemm, cudaFuncAttributeMaxDynamicSharedMemorySize, GEMM_SMEM_H);

    // 0) fused fp32 -> fp16 conversions (x, Wqkv, Wproj)
    f2h_all<<<N_CVT / 2048, 256>>>(x, Wqkv, Wproj, xh, wqkvh, wprojh);

    // 1) QKV projection -> fp16 qkv
    hgemm<<<dim3(3 * Dq / BNh, Mrows / BMh), 256, GEMM_SMEM_H>>>(
        xh, wqkvh, bqkv, qkvh, 3 * Dq, Dq);
    // 2) Windowed attention (tensor cores, 4 windows/CTA, double-buffered)
    win_attn_tc<<<(Bq * Hq * (Lq / Wq)) / UPC, 128>>>(qkvh, attnh);
    // 3) Output projection + bias -> fp16 proj
    hgemm<<<dim3(Dq / BNh, Mrows / BMh), 256, GEMM_SMEM_H>>>(
        attnh, wprojh, bproj, projh, Dq, Dq);
    // 4) Residual (fp16 x) + LayerNorm -> out
    res_ln_k<<<Mrows, 256>>>(projh, xh, gamma, beta, out);
}